// round 2
// baseline (speedup 1.0000x reference)
#include <cuda_runtime.h>
#include <math.h>

#define TT 128
#define BB 128
#define ZD 64
#define AD 64
#define KK 32
#define SD 68
#define TB (TT*BB)

// ---------------- device scratch (allocation-free rule) ----------------
__device__ float g_Q[ZD*ZD];
__device__ float g_R[AD*AD];
__device__ float g_w[TB*KK];
__device__ float g_A[(size_t)TB*4096];
__device__ float g_C[(size_t)TB*4096];
__device__ float g_J[(size_t)TB*4096];
__device__ float g_fm[TB*ZD];
__device__ float g_mp0[BB*ZD];

// ---------------- helpers ----------------
__device__ __forceinline__ float4 ffma4(float s, float4 v, float4 a){
    a.x = fmaf(s, v.x, a.x); a.y = fmaf(s, v.y, a.y);
    a.z = fmaf(s, v.z, a.z); a.w = fmaf(s, v.w, a.w);
    return a;
}
__device__ __forceinline__ float dot4acc(float4 a, float4 b, float acc){
    acc = fmaf(a.x, b.x, acc); acc = fmaf(a.y, b.y, acc);
    acc = fmaf(a.z, b.z, acc); acc = fmaf(a.w, b.w, acc);
    return acc;
}

// O = A @ B   (all smem, row-major stride SD), 256 threads, ends synced
__device__ __forceinline__ void mm_nn(const float* __restrict__ A,
                                      const float* __restrict__ B,
                                      float* __restrict__ O, int tid)
{
    const int tx4 = (tid & 15) << 2;
    const int ty4 = (tid >> 4) << 2;
    float4 a0c={0,0,0,0}, a1c={0,0,0,0}, a2c={0,0,0,0}, a3c={0,0,0,0};
    #pragma unroll 4
    for (int k0 = 0; k0 < 64; k0 += 4){
        float4 a0 = *(const float4*)(A + (ty4+0)*SD + k0);
        float4 a1 = *(const float4*)(A + (ty4+1)*SD + k0);
        float4 a2 = *(const float4*)(A + (ty4+2)*SD + k0);
        float4 a3 = *(const float4*)(A + (ty4+3)*SD + k0);
        float4 b0 = *(const float4*)(B + (k0+0)*SD + tx4);
        float4 b1 = *(const float4*)(B + (k0+1)*SD + tx4);
        float4 b2 = *(const float4*)(B + (k0+2)*SD + tx4);
        float4 b3 = *(const float4*)(B + (k0+3)*SD + tx4);
        a0c=ffma4(a0.x,b0,a0c); a0c=ffma4(a0.y,b1,a0c); a0c=ffma4(a0.z,b2,a0c); a0c=ffma4(a0.w,b3,a0c);
        a1c=ffma4(a1.x,b0,a1c); a1c=ffma4(a1.y,b1,a1c); a1c=ffma4(a1.z,b2,a1c); a1c=ffma4(a1.w,b3,a1c);
        a2c=ffma4(a2.x,b0,a2c); a2c=ffma4(a2.y,b1,a2c); a2c=ffma4(a2.z,b2,a2c); a2c=ffma4(a2.w,b3,a2c);
        a3c=ffma4(a3.x,b0,a3c); a3c=ffma4(a3.y,b1,a3c); a3c=ffma4(a3.z,b2,a3c); a3c=ffma4(a3.w,b3,a3c);
    }
    *(float4*)(O + (ty4+0)*SD + tx4) = a0c;
    *(float4*)(O + (ty4+1)*SD + tx4) = a1c;
    *(float4*)(O + (ty4+2)*SD + tx4) = a2c;
    *(float4*)(O + (ty4+3)*SD + tx4) = a3c;
    __syncthreads();
}

// O = A @ B    writing to GLOBAL memory with row stride 64; ends synced
__device__ __forceinline__ void mm_nn_g(const float* __restrict__ A,
                                        const float* __restrict__ B,
                                        float* __restrict__ O, int tid)
{
    const int tx4 = (tid & 15) << 2;
    const int ty4 = (tid >> 4) << 2;
    float4 a0c={0,0,0,0}, a1c={0,0,0,0}, a2c={0,0,0,0}, a3c={0,0,0,0};
    #pragma unroll 4
    for (int k0 = 0; k0 < 64; k0 += 4){
        float4 a0 = *(const float4*)(A + (ty4+0)*SD + k0);
        float4 a1 = *(const float4*)(A + (ty4+1)*SD + k0);
        float4 a2 = *(const float4*)(A + (ty4+2)*SD + k0);
        float4 a3 = *(const float4*)(A + (ty4+3)*SD + k0);
        float4 b0 = *(const float4*)(B + (k0+0)*SD + tx4);
        float4 b1 = *(const float4*)(B + (k0+1)*SD + tx4);
        float4 b2 = *(const float4*)(B + (k0+2)*SD + tx4);
        float4 b3 = *(const float4*)(B + (k0+3)*SD + tx4);
        a0c=ffma4(a0.x,b0,a0c); a0c=ffma4(a0.y,b1,a0c); a0c=ffma4(a0.z,b2,a0c); a0c=ffma4(a0.w,b3,a0c);
        a1c=ffma4(a1.x,b0,a1c); a1c=ffma4(a1.y,b1,a1c); a1c=ffma4(a1.z,b2,a1c); a1c=ffma4(a1.w,b3,a1c);
        a2c=ffma4(a2.x,b0,a2c); a2c=ffma4(a2.y,b1,a2c); a2c=ffma4(a2.z,b2,a2c); a2c=ffma4(a2.w,b3,a2c);
        a3c=ffma4(a3.x,b0,a3c); a3c=ffma4(a3.y,b1,a3c); a3c=ffma4(a3.z,b2,a3c); a3c=ffma4(a3.w,b3,a3c);
    }
    *(float4*)(O + (ty4+0)*64 + tx4) = a0c;
    *(float4*)(O + (ty4+1)*64 + tx4) = a1c;
    *(float4*)(O + (ty4+2)*64 + tx4) = a2c;
    *(float4*)(O + (ty4+3)*64 + tx4) = a3c;
    __syncthreads();
}

// O = A @ B^T  (+ Add if ADD); ends synced
template<bool ADD>
__device__ __forceinline__ void mm_nt(const float* __restrict__ A,
                                      const float* __restrict__ B,
                                      const float* __restrict__ Add,
                                      float* __restrict__ O, int tid)
{
    const int tx4 = (tid & 15) << 2;
    const int ty4 = (tid >> 4) << 2;
    float4 a0c={0,0,0,0}, a1c={0,0,0,0}, a2c={0,0,0,0}, a3c={0,0,0,0};
    #pragma unroll 4
    for (int k0 = 0; k0 < 64; k0 += 4){
        float4 a0 = *(const float4*)(A + (ty4+0)*SD + k0);
        float4 a1 = *(const float4*)(A + (ty4+1)*SD + k0);
        float4 a2 = *(const float4*)(A + (ty4+2)*SD + k0);
        float4 a3 = *(const float4*)(A + (ty4+3)*SD + k0);
        float4 c0 = *(const float4*)(B + (tx4+0)*SD + k0);
        float4 c1 = *(const float4*)(B + (tx4+1)*SD + k0);
        float4 c2 = *(const float4*)(B + (tx4+2)*SD + k0);
        float4 c3 = *(const float4*)(B + (tx4+3)*SD + k0);
        a0c.x=dot4acc(a0,c0,a0c.x); a0c.y=dot4acc(a0,c1,a0c.y); a0c.z=dot4acc(a0,c2,a0c.z); a0c.w=dot4acc(a0,c3,a0c.w);
        a1c.x=dot4acc(a1,c0,a1c.x); a1c.y=dot4acc(a1,c1,a1c.y); a1c.z=dot4acc(a1,c2,a1c.z); a1c.w=dot4acc(a1,c3,a1c.w);
        a2c.x=dot4acc(a2,c0,a2c.x); a2c.y=dot4acc(a2,c1,a2c.y); a2c.z=dot4acc(a2,c2,a2c.z); a2c.w=dot4acc(a2,c3,a2c.w);
        a3c.x=dot4acc(a3,c0,a3c.x); a3c.y=dot4acc(a3,c1,a3c.y); a3c.z=dot4acc(a3,c2,a3c.z); a3c.w=dot4acc(a3,c3,a3c.w);
    }
    #pragma unroll
    for (int i = 0; i < 4; i++){
        float4 v = (i==0)?a0c:((i==1)?a1c:((i==2)?a2c:a3c));
        if (ADD){
            float4 ad = *(const float4*)(Add + (ty4+i)*SD + tx4);
            v.x += ad.x; v.y += ad.y; v.z += ad.z; v.w += ad.w;
        }
        *(float4*)(O + (ty4+i)*SD + tx4) = v;
    }
    __syncthreads();
}

// O = Sub - A^T @ B ; ends synced
__device__ __forceinline__ void mm_tn_sub(const float* __restrict__ A,
                                          const float* __restrict__ B,
                                          const float* __restrict__ Sub,
                                          float* __restrict__ O, int tid)
{
    const int tx4 = (tid & 15) << 2;
    const int ty4 = (tid >> 4) << 2;
    float4 a0c={0,0,0,0}, a1c={0,0,0,0}, a2c={0,0,0,0}, a3c={0,0,0,0};
    #pragma unroll 4
    for (int k = 0; k < 64; k++){
        float4 av = *(const float4*)(A + k*SD + ty4);
        float4 bv = *(const float4*)(B + k*SD + tx4);
        a0c = ffma4(av.x, bv, a0c);
        a1c = ffma4(av.y, bv, a1c);
        a2c = ffma4(av.z, bv, a2c);
        a3c = ffma4(av.w, bv, a3c);
    }
    #pragma unroll
    for (int i = 0; i < 4; i++){
        float4 v = (i==0)?a0c:((i==1)?a1c:((i==2)?a2c:a3c));
        float4 s = *(const float4*)(Sub + (ty4+i)*SD + tx4);
        v.x = s.x - v.x; v.y = s.y - v.y; v.z = s.z - v.z; v.w = s.w - v.w;
        *(float4*)(O + (ty4+i)*SD + tx4) = v;
    }
    __syncthreads();
}

// X = 0.5*(X + X^T) in place; ends synced
__device__ __forceinline__ void symm(float* __restrict__ X, int tid){
    const int r = tid >> 2, jb = (tid & 3) << 4;
    float v[16];
    #pragma unroll
    for (int u = 0; u < 16; u++){
        int j = jb + u;
        v[u] = 0.5f*(X[r*SD + j] + X[j*SD + r]);
    }
    __syncthreads();
    #pragma unroll
    for (int u = 0; u < 16; u++) X[r*SD + jb + u] = v[u];
    __syncthreads();
}

// In-place Gauss-Jordan inverse of 64x64 SPD matrix in smem (no pivoting); ends synced
__device__ __forceinline__ void gj_inv(float* __restrict__ M, float* __restrict__ colv,
                                       float* __restrict__ prow, float* __restrict__ sc, int tid)
{
    const int r  = tid >> 2;
    const int q  = tid & 3;
    const int jb = q << 4;
    for (int p = 0; p < 64; p++){
        if (tid < 64)           colv[tid]    = M[tid*SD + p];
        else if (tid < 128)     prow[tid-64] = M[p*SD + (tid-64)];
        else if (tid == 128)    sc[0] = 1.0f / M[p*SD + p];
        __syncthreads();
        const float pinv = sc[0];
        float* row = M + r*SD;
        float cr = colv[r]*pinv;
        if (r == p){
            #pragma unroll
            for (int u = 0; u < 4; u++){
                float4 pr = *(const float4*)(prow + jb + 4*u);
                float4 v; v.x=pr.x*pinv; v.y=pr.y*pinv; v.z=pr.z*pinv; v.w=pr.w*pinv;
                *(float4*)(row + jb + 4*u) = v;
            }
        } else {
            #pragma unroll
            for (int u = 0; u < 4; u++){
                float4 pr = *(const float4*)(prow + jb + 4*u);
                float4 m  = *(const float4*)(row + jb + 4*u);
                m.x -= cr*pr.x; m.y -= cr*pr.y; m.z -= cr*pr.z; m.w -= cr*pr.w;
                *(float4*)(row + jb + 4*u) = m;
            }
        }
        if ((p >> 4) == q) row[p] = (r == p) ? pinv : -cr;
        __syncthreads();
    }
}

// ---------------- kernel 1: Q/R construction ----------------
__global__ void qr_kernel(const float* __restrict__ Lq, const float* __restrict__ Lr){
    __shared__ float sL[64*65];
    const float* L = (blockIdx.x == 0) ? Lq : Lr;
    float* O = (blockIdx.x == 0) ? g_Q : g_R;
    int tid = threadIdx.x;
    for (int i = tid; i < 4096; i += 256) sL[(i>>6)*65 + (i&63)] = L[i];
    __syncthreads();
    for (int e = tid; e < 4096; e += 256){
        int i = e >> 6, j = e & 63;
        float acc = (i == j) ? 1e-3f : 0.0f;
        #pragma unroll 8
        for (int k = 0; k < 64; k++) acc += sL[i*65+k]*sL[j*65+k];
        O[e] = acc;
    }
}

// ---------------- kernel 2: LSTM + softmax weights ----------------
__global__ void __launch_bounds__(128) lstm_kernel(
    const float* __restrict__ x,
    const float* __restrict__ Wih, const float* __restrict__ Whh,
    const float* __restrict__ bih, const float* __restrict__ bhh)
{
    extern __shared__ float sm[];
    float* sWih = sm;                 // 128*65
    float* sWhh = sWih + 128*65;      // 128*33
    float* sx   = sWhh + 128*33;      // 128*64
    float* sh   = sx + 128*64;        // 32
    float* sg   = sh + 32;            // 128
    const int b = blockIdx.x, tid = threadIdx.x;
    for (int i = tid; i < 128*64; i += 128) sWih[(i>>6)*65 + (i&63)] = Wih[i];
    for (int i = tid; i < 128*32; i += 128) sWhh[(i>>5)*33 + (i&31)] = Whh[i];
    for (int i = tid; i < TT*64;  i += 128) sx[i] = x[((i>>6)*BB + b)*64 + (i&63)];
    if (tid < 32) sh[tid] = 0.0f;
    const float bias = bih[tid] + bhh[tid];
    float c = 0.0f;
    __syncthreads();
    for (int t = 0; t < TT; t++){
        float acc = bias;
        const float* wr = sWih + tid*65;
        const float* xr = sx + t*64;
        #pragma unroll 8
        for (int j = 0; j < 64; j++) acc += wr[j]*xr[j];
        const float* hr = sWhh + tid*33;
        #pragma unroll 8
        for (int j = 0; j < 32; j++) acc += hr[j]*sh[j];
        sg[tid] = acc;
        __syncthreads();
        if (tid < 32){
            float ig = 1.0f/(1.0f+expf(-sg[tid]));
            float fg = 1.0f/(1.0f+expf(-sg[32+tid]));
            float gg = tanhf(sg[64+tid]);
            float og = 1.0f/(1.0f+expf(-sg[96+tid]));
            c = fg*c + ig*gg;
            float h = og*tanhf(c);
            sh[tid] = h;
            float m = h;
            for (int o = 16; o; o >>= 1) m = fmaxf(m, __shfl_xor_sync(0xffffffffu, m, o));
            float e = expf(h - m);
            float s = e;
            for (int o = 16; o; o >>= 1) s += __shfl_xor_sync(0xffffffffu, s, o);
            g_w[(t*BB + b)*KK + tid] = e/s;
        }
        __syncthreads();
    }
}

// ---------------- kernel 3: mix A_t, C_t from basis ----------------
__global__ void mix_kernel(const float* __restrict__ AK, const float* __restrict__ CK){
    __shared__ float sB[32*256];
    __shared__ float sw[64*33];
    const int chunk = blockIdx.x;     // 0..15   (256 ij each)
    const int grp   = blockIdx.y;     // 0..255  (64 tb each)
    const float* Bsrc = (blockIdx.z == 0) ? AK : CK;
    float* Odst = (blockIdx.z == 0) ? g_A : g_C;
    const int tid = threadIdx.x;      // 256
    for (int i = tid; i < 32*256; i += 256)
        sB[i] = Bsrc[(i>>8)*4096 + chunk*256 + (i&255)];
    for (int i = tid; i < 64*32; i += 256)
        sw[(i>>5)*33 + (i&31)] = g_w[((size_t)grp*64 + (i>>5))*KK + (i&31)];
    __syncthreads();
    const int j = tid;
    for (int tb = 0; tb < 64; tb++){
        float acc = 0.0f;
        const float* wv = sw + tb*33;
        #pragma unroll
        for (int k = 0; k < 32; k++) acc += wv[k]*sB[k*256 + j];
        Odst[(size_t)(grp*64 + tb)*4096 + chunk*256 + j] = acc;
    }
}

// ---------------- kernel 4: Kalman filter (+J gains) ----------------
__global__ void __launch_bounds__(256, 1) filter_kernel(
    const float* __restrict__ as_,
    const float* __restrict__ init_mean,
    const float* __restrict__ init_cov)
{
    extern __shared__ float sm[];
    float* Qs = sm;
    float* Rs = Qs + 64*SD;
    float* As = Rs + 64*SD;
    float* Cs = As + 64*SD;
    float* P  = Cs + 64*SD;
    float* M1 = P  + 64*SD;
    float* M2 = M1 + 64*SD;
    float* M3 = M2 + 64*SD;
    float* M4 = M3 + 64*SD;
    float* vmean = M4 + 64*SD;
    float* vmt   = vmean + 64;
    float* vmn   = vmt + 64;
    float* vin   = vmn + 64;
    float* vat   = vin + 64;
    float* colv  = vat + 64;
    float* prow  = colv + 64;
    float* sc    = prow + 64;
    const int b = blockIdx.x, tid = threadIdx.x;

    for (int i = tid; i < 4096; i += 256){
        int r = i >> 6, c = i & 63;
        P[r*SD + c]  = init_cov[i];
        Qs[r*SD + c] = g_Q[i];
        Rs[r*SD + c] = g_R[i];
    }
    if (tid < 64) vmean[tid] = init_mean[tid];
    __syncthreads();

    for (int t = 0; t < TT; t++){
        const int tb = t*BB + b;
        const float* gA = g_A + (size_t)tb*4096;
        const float* gC = g_C + (size_t)tb*4096;
        for (int i4 = tid; i4 < 1024; i4 += 256){
            int r = i4 >> 4, c4 = (i4 & 15) << 2;
            *(float4*)(As + r*SD + c4) = *(const float4*)(gA + r*64 + c4);
            *(float4*)(Cs + r*SD + c4) = *(const float4*)(gC + r*64 + c4);
        }
        if (tid < 64) vat[tid] = as_[(size_t)tb*64 + tid];
        __syncthreads();

        mm_nn(Cs, P, M1, tid);                  // M1 = C P
        mm_nt<true>(M1, Cs, Rs, M2, tid);       // M2 = S = CP C^T + R
        gj_inv(M2, colv, prow, sc, tid);        // M2 = S^-1
        mm_nn(M2, M1, M3, tid);                 // M3 = Kt = S^-1 C P   (= K^T)

        if (tid < 64){                          // innov = a_t - C mean_p
            float acc = 0.0f;
            #pragma unroll 8
            for (int j = 0; j < 64; j++) acc += Cs[tid*SD + j]*vmean[j];
            vin[tid] = vat[tid] - acc;
        }
        __syncthreads();
        if (tid < 64){                          // mean_t = mean_p + Kt^T innov
            float acc = vmean[tid];
            #pragma unroll 8
            for (int j = 0; j < 64; j++) acc += M3[j*SD + tid]*vin[j];
            vmt[tid] = acc;
            g_fm[(size_t)tb*64 + tid] = acc;
        }
        __syncthreads();

        mm_tn_sub(M3, M1, P, M2, tid);          // M2 = covt = P - Kt^T (CP)
        symm(M2, tid);
        mm_nn(As, M2, M4, tid);                 // M4 = A covt
        mm_nt<true>(M4, As, Qs, M1, tid);       // M1 = Pn = A covt A^T + Q
        symm(M1, tid);

        if (tid < 64){                          // mean_n = A mean_t
            float acc = 0.0f;
            #pragma unroll 8
            for (int j = 0; j < 64; j++) acc += As[tid*SD + j]*vmt[j];
            vmn[tid] = acc;
            if (t == 0) g_mp0[b*64 + tid] = acc;
        }
        __syncthreads();

        for (int i4 = tid; i4 < 1024; i4 += 256){   // M3 = copy(Pn)
            int r = i4 >> 4, c4 = (i4 & 15) << 2;
            *(float4*)(M3 + r*SD + c4) = *(const float4*)(M1 + r*SD + c4);
        }
        __syncthreads();
        gj_inv(M3, colv, prow, sc, tid);        // M3 = Pn^-1
        mm_nt<false>(M2, As, (const float*)0, M4, tid);  // M4 = covt A^T
        mm_nn_g(M4, M3, g_J + (size_t)tb*4096, tid);     // J -> gmem

        for (int i4 = tid; i4 < 1024; i4 += 256){   // P <- Pn
            int r = i4 >> 4, c4 = (i4 & 15) << 2;
            *(float4*)(P + r*SD + c4) = *(const float4*)(M1 + r*SD + c4);
        }
        if (tid < 64) vmean[tid] = vmn[tid];
        __syncthreads();
    }
}

// ---------------- kernel 5: RTS smoother (means only) ----------------
__global__ void __launch_bounds__(256) smooth_kernel(float* __restrict__ out)
{
    __shared__ float sJ[64*65];
    __shared__ float sv[64];
    __shared__ float sms[64];
    __shared__ float smp0[64];
    const int b = blockIdx.x, tid = threadIdx.x;

    if (tid < 64){
        float m = g_fm[(size_t)((TT-1)*BB + b)*64 + tid];
        sms[tid] = m;
        out[(size_t)((TT-1)*BB + b)*64 + tid] = m;
        smp0[tid] = g_mp0[b*64 + tid];
    }
    float4 rj[4];
    {
        const float* gJ = g_J + (size_t)((TT-2)*BB + b)*4096;
        #pragma unroll
        for (int u = 0; u < 4; u++) rj[u] = *(const float4*)(gJ + (size_t)(tid + 256*u)*4);
    }
    __syncthreads();

    for (int t = TT-2; t >= 0; t--){
        #pragma unroll
        for (int u = 0; u < 4; u++){
            int idx = tid + 256*u;
            int row = idx >> 4, c4 = (idx & 15) << 2;
            sJ[row*65 + c4 + 0] = rj[u].x;
            sJ[row*65 + c4 + 1] = rj[u].y;
            sJ[row*65 + c4 + 2] = rj[u].z;
            sJ[row*65 + c4 + 3] = rj[u].w;
        }
        if (tid < 64) sv[tid] = sms[tid] - smp0[tid];
        __syncthreads();
        if (t > 0){
            const float* gJ = g_J + (size_t)((t-1)*BB + b)*4096;
            #pragma unroll
            for (int u = 0; u < 4; u++) rj[u] = *(const float4*)(gJ + (size_t)(tid + 256*u)*4);
        }
        if (tid < 64){
            float acc = g_fm[(size_t)(t*BB + b)*64 + tid];
            #pragma unroll 8
            for (int j = 0; j < 64; j++) acc += sJ[tid*65 + j]*sv[j];
            out[(size_t)(t*BB + b)*64 + tid] = acc;
            sms[tid] = acc;
        }
        __syncthreads();
    }
}

// ---------------- launch ----------------
extern "C" void kernel_launch(void* const* d_in, const int* in_sizes, int n_in,
                              void* d_out, int out_size)
{
    const float* as_ = (const float*)d_in[0];
    const float* AK  = (const float*)d_in[1];
    const float* CK  = (const float*)d_in[2];
    const float* Lq  = (const float*)d_in[3];
    const float* Lr  = (const float*)d_in[4];
    const float* Wih = (const float*)d_in[5];
    const float* Whh = (const float*)d_in[6];
    const float* bih = (const float*)d_in[7];
    const float* bhh = (const float*)d_in[8];
    const float* im  = (const float*)d_in[9];
    const float* ic  = (const float*)d_in[10];
    float* out = (float*)d_out;

    const int lstm_smem = (128*65 + 128*33 + 128*64 + 32 + 128)*4;
    const int filt_smem = (9*64*SD + 8*64)*4;
    cudaFuncSetAttribute(lstm_kernel,   cudaFuncAttributeMaxDynamicSharedMemorySize, lstm_smem);
    cudaFuncSetAttribute(filter_kernel, cudaFuncAttributeMaxDynamicSharedMemorySize, filt_smem);

    qr_kernel<<<2, 256>>>(Lq, Lr);
    lstm_kernel<<<BB, 128, lstm_smem>>>(as_, Wih, Whh, bih, bhh);
    mix_kernel<<<dim3(16, 256, 2), 256>>>(AK, CK);
    filter_kernel<<<BB, 256, filt_smem>>>(as_, im, ic);
    smooth_kernel<<<BB, 256>>>(out);
}

// round 3
// speedup vs baseline: 1.6037x; 1.6037x over previous
#include <cuda_runtime.h>
#include <math.h>

#define TT 128
#define BB 128
#define ZD 64
#define AD 64
#define KK 32
#define SD 68
#define TB (TT*BB)

// ---------------- device scratch (allocation-free rule) ----------------
__device__ float g_Q[ZD*ZD];
__device__ float g_R[AD*AD];
__device__ float g_w[TB*KK];
__device__ float g_A[(size_t)TB*4096];
__device__ float g_C[(size_t)TB*4096];
__device__ float g_J[(size_t)TB*4096];
__device__ float g_fm[TB*ZD];
__device__ float g_mp0[BB*ZD];

// ---------------- helpers ----------------
__device__ __forceinline__ float4 ffma4(float s, float4 v, float4 a){
    a.x = fmaf(s, v.x, a.x); a.y = fmaf(s, v.y, a.y);
    a.z = fmaf(s, v.z, a.z); a.w = fmaf(s, v.w, a.w);
    return a;
}
__device__ __forceinline__ float dot4acc(float4 a, float4 b, float acc){
    acc = fmaf(a.x, b.x, acc); acc = fmaf(a.y, b.y, acc);
    acc = fmaf(a.z, b.z, acc); acc = fmaf(a.w, b.w, acc);
    return acc;
}

// O = A @ B   (all smem, row-major stride SD), 256 threads, ends synced
__device__ __forceinline__ void mm_nn(const float* __restrict__ A,
                                      const float* __restrict__ B,
                                      float* __restrict__ O, int tid)
{
    const int tx4 = (tid & 15) << 2;
    const int ty4 = (tid >> 4) << 2;
    float4 a0c={0,0,0,0}, a1c={0,0,0,0}, a2c={0,0,0,0}, a3c={0,0,0,0};
    #pragma unroll 4
    for (int k0 = 0; k0 < 64; k0 += 4){
        float4 a0 = *(const float4*)(A + (ty4+0)*SD + k0);
        float4 a1 = *(const float4*)(A + (ty4+1)*SD + k0);
        float4 a2 = *(const float4*)(A + (ty4+2)*SD + k0);
        float4 a3 = *(const float4*)(A + (ty4+3)*SD + k0);
        float4 b0 = *(const float4*)(B + (k0+0)*SD + tx4);
        float4 b1 = *(const float4*)(B + (k0+1)*SD + tx4);
        float4 b2 = *(const float4*)(B + (k0+2)*SD + tx4);
        float4 b3 = *(const float4*)(B + (k0+3)*SD + tx4);
        a0c=ffma4(a0.x,b0,a0c); a0c=ffma4(a0.y,b1,a0c); a0c=ffma4(a0.z,b2,a0c); a0c=ffma4(a0.w,b3,a0c);
        a1c=ffma4(a1.x,b0,a1c); a1c=ffma4(a1.y,b1,a1c); a1c=ffma4(a1.z,b2,a1c); a1c=ffma4(a1.w,b3,a1c);
        a2c=ffma4(a2.x,b0,a2c); a2c=ffma4(a2.y,b1,a2c); a2c=ffma4(a2.z,b2,a2c); a2c=ffma4(a2.w,b3,a2c);
        a3c=ffma4(a3.x,b0,a3c); a3c=ffma4(a3.y,b1,a3c); a3c=ffma4(a3.z,b2,a3c); a3c=ffma4(a3.w,b3,a3c);
    }
    *(float4*)(O + (ty4+0)*SD + tx4) = a0c;
    *(float4*)(O + (ty4+1)*SD + tx4) = a1c;
    *(float4*)(O + (ty4+2)*SD + tx4) = a2c;
    *(float4*)(O + (ty4+3)*SD + tx4) = a3c;
    __syncthreads();
}

// O = A @ B^T  (+ Add if ADD); ends synced
template<bool ADD>
__device__ __forceinline__ void mm_nt(const float* __restrict__ A,
                                      const float* __restrict__ B,
                                      const float* __restrict__ Add,
                                      float* __restrict__ O, int tid)
{
    const int tx4 = (tid & 15) << 2;
    const int ty4 = (tid >> 4) << 2;
    float4 a0c={0,0,0,0}, a1c={0,0,0,0}, a2c={0,0,0,0}, a3c={0,0,0,0};
    #pragma unroll 4
    for (int k0 = 0; k0 < 64; k0 += 4){
        float4 a0 = *(const float4*)(A + (ty4+0)*SD + k0);
        float4 a1 = *(const float4*)(A + (ty4+1)*SD + k0);
        float4 a2 = *(const float4*)(A + (ty4+2)*SD + k0);
        float4 a3 = *(const float4*)(A + (ty4+3)*SD + k0);
        float4 c0 = *(const float4*)(B + (tx4+0)*SD + k0);
        float4 c1 = *(const float4*)(B + (tx4+1)*SD + k0);
        float4 c2 = *(const float4*)(B + (tx4+2)*SD + k0);
        float4 c3 = *(const float4*)(B + (tx4+3)*SD + k0);
        a0c.x=dot4acc(a0,c0,a0c.x); a0c.y=dot4acc(a0,c1,a0c.y); a0c.z=dot4acc(a0,c2,a0c.z); a0c.w=dot4acc(a0,c3,a0c.w);
        a1c.x=dot4acc(a1,c0,a1c.x); a1c.y=dot4acc(a1,c1,a1c.y); a1c.z=dot4acc(a1,c2,a1c.z); a1c.w=dot4acc(a1,c3,a1c.w);
        a2c.x=dot4acc(a2,c0,a2c.x); a2c.y=dot4acc(a2,c1,a2c.y); a2c.z=dot4acc(a2,c2,a2c.z); a2c.w=dot4acc(a2,c3,a2c.w);
        a3c.x=dot4acc(a3,c0,a3c.x); a3c.y=dot4acc(a3,c1,a3c.y); a3c.z=dot4acc(a3,c2,a3c.z); a3c.w=dot4acc(a3,c3,a3c.w);
    }
    #pragma unroll
    for (int i = 0; i < 4; i++){
        float4 v = (i==0)?a0c:((i==1)?a1c:((i==2)?a2c:a3c));
        if (ADD){
            float4 ad = *(const float4*)(Add + (ty4+i)*SD + tx4);
            v.x += ad.x; v.y += ad.y; v.z += ad.z; v.w += ad.w;
        }
        *(float4*)(O + (ty4+i)*SD + tx4) = v;
    }
    __syncthreads();
}

// O = Sub - A^T @ B ; ends synced
__device__ __forceinline__ void mm_tn_sub(const float* __restrict__ A,
                                          const float* __restrict__ B,
                                          const float* __restrict__ Sub,
                                          float* __restrict__ O, int tid)
{
    const int tx4 = (tid & 15) << 2;
    const int ty4 = (tid >> 4) << 2;
    float4 a0c={0,0,0,0}, a1c={0,0,0,0}, a2c={0,0,0,0}, a3c={0,0,0,0};
    #pragma unroll 4
    for (int k = 0; k < 64; k++){
        float4 av = *(const float4*)(A + k*SD + ty4);
        float4 bv = *(const float4*)(B + k*SD + tx4);
        a0c = ffma4(av.x, bv, a0c);
        a1c = ffma4(av.y, bv, a1c);
        a2c = ffma4(av.z, bv, a2c);
        a3c = ffma4(av.w, bv, a3c);
    }
    #pragma unroll
    for (int i = 0; i < 4; i++){
        float4 v = (i==0)?a0c:((i==1)?a1c:((i==2)?a2c:a3c));
        float4 s = *(const float4*)(Sub + (ty4+i)*SD + tx4);
        v.x = s.x - v.x; v.y = s.y - v.y; v.z = s.z - v.z; v.w = s.w - v.w;
        *(float4*)(O + (ty4+i)*SD + tx4) = v;
    }
    __syncthreads();
}

// O(gmem, row stride 64) = A^T @ B ; ends synced
__device__ __forceinline__ void mm_tn_g(const float* __restrict__ A,
                                        const float* __restrict__ B,
                                        float* __restrict__ O, int tid)
{
    const int tx4 = (tid & 15) << 2;
    const int ty4 = (tid >> 4) << 2;
    float4 a0c={0,0,0,0}, a1c={0,0,0,0}, a2c={0,0,0,0}, a3c={0,0,0,0};
    #pragma unroll 4
    for (int k = 0; k < 64; k++){
        float4 av = *(const float4*)(A + k*SD + ty4);
        float4 bv = *(const float4*)(B + k*SD + tx4);
        a0c = ffma4(av.x, bv, a0c);
        a1c = ffma4(av.y, bv, a1c);
        a2c = ffma4(av.z, bv, a2c);
        a3c = ffma4(av.w, bv, a3c);
    }
    *(float4*)(O + (ty4+0)*64 + tx4) = a0c;
    *(float4*)(O + (ty4+1)*64 + tx4) = a1c;
    *(float4*)(O + (ty4+2)*64 + tx4) = a2c;
    *(float4*)(O + (ty4+3)*64 + tx4) = a3c;
    __syncthreads();
}

// X = 0.5*(X + X^T) in place; ends synced
__device__ __forceinline__ void symm(float* __restrict__ X, int tid){
    const int r = tid >> 2, jb = (tid & 3) << 4;
    float v[16];
    #pragma unroll
    for (int u = 0; u < 16; u++){
        int j = jb + u;
        v[u] = 0.5f*(X[r*SD + j] + X[j*SD + r]);
    }
    __syncthreads();
    #pragma unroll
    for (int u = 0; u < 16; u++) X[r*SD + jb + u] = v[u];
    __syncthreads();
}

// ---------------- register-resident Gauss-Jordan inverse -------------------
// In (smem, stride SD, symmetric) -> Out (smem, stride SD). 256 threads.
// Thread (r=tid>>2, q=tid&3) holds row r cols [16q,16q+16) in registers.
// Per pivot: ONE __syncthreads. Uses sign-symmetry of GJ on symmetric input
// (M[r][p] = -M[p][r] for r<p, = M[p][r] for r>=p) so the pivot column comes
// from the pivot row. The +1 (row) / -1 (col) augmentation makes the update a
// single uniform rank-1 FMA: M' = M - (u/piv) (x) v.
__device__ __forceinline__ void gj_reg(const float* __restrict__ In,
                                       float* __restrict__ Out,
                                       float* __restrict__ prowbuf, // 2*64 floats, 16B aligned
                                       float* __restrict__ scbuf,   // 2 floats
                                       int tid)
{
    const int r  = tid >> 2;
    const int cb = (tid & 3) << 4;
    float m[16];
    #pragma unroll
    for (int u = 0; u < 4; u++){
        float4 t = *(const float4*)(In + r*SD + cb + 4*u);
        m[4*u+0]=t.x; m[4*u+1]=t.y; m[4*u+2]=t.z; m[4*u+3]=t.w;
    }
    __syncthreads();   // registers loaded; prow buffers free
    #pragma unroll 1
    for (int p = 0; p < 64; p++){
        float* prb = prowbuf + ((p & 1) << 6);
        if (r == p){
            if ((cb >> 4) == (p >> 4)){
                float pv = m[0];
                #pragma unroll
                for (int j = 1; j < 16; j++) if (cb + j == p) pv = m[j];
                scbuf[p & 1] = pv;
            }
            #pragma unroll
            for (int u = 0; u < 4; u++){
                float4 t;
                t.x = m[4*u+0] + ((cb + 4*u + 0 == p) ? 1.0f : 0.0f);
                t.y = m[4*u+1] + ((cb + 4*u + 1 == p) ? 1.0f : 0.0f);
                t.z = m[4*u+2] + ((cb + 4*u + 2 == p) ? 1.0f : 0.0f);
                t.w = m[4*u+3] + ((cb + 4*u + 3 == p) ? 1.0f : 0.0f);
                *(float4*)(prb + cb + 4*u) = t;
            }
        }
        __syncthreads();
        const float piv = scbuf[p & 1];
        const float pivinv = __frcp_rn(piv);
        float urow = prb[r];
        float u_ = (r < p) ? -urow : ((r == p) ? urow - 2.0f : urow);
        const float f = u_ * pivinv;
        #pragma unroll
        for (int u = 0; u < 4; u++){
            float4 t = *(const float4*)(prb + cb + 4*u);
            m[4*u+0] = fmaf(-f, t.x, m[4*u+0]);
            m[4*u+1] = fmaf(-f, t.y, m[4*u+1]);
            m[4*u+2] = fmaf(-f, t.z, m[4*u+2]);
            m[4*u+3] = fmaf(-f, t.w, m[4*u+3]);
        }
    }
    #pragma unroll
    for (int u = 0; u < 4; u++){
        float4 t; t.x=m[4*u+0]; t.y=m[4*u+1]; t.z=m[4*u+2]; t.w=m[4*u+3];
        *(float4*)(Out + r*SD + cb + 4*u) = t;
    }
    __syncthreads();
}

// ---------------- kernel 1: Q/R construction ----------------
__global__ void qr_kernel(const float* __restrict__ Lq, const float* __restrict__ Lr){
    __shared__ float sL[64*65];
    const float* L = (blockIdx.x == 0) ? Lq : Lr;
    float* O = (blockIdx.x == 0) ? g_Q : g_R;
    int tid = threadIdx.x;
    for (int i = tid; i < 4096; i += 256) sL[(i>>6)*65 + (i&63)] = L[i];
    __syncthreads();
    for (int e = tid; e < 4096; e += 256){
        int i = e >> 6, j = e & 63;
        float acc = (i == j) ? 1e-3f : 0.0f;
        #pragma unroll 8
        for (int k = 0; k < 64; k++) acc += sL[i*65+k]*sL[j*65+k];
        O[e] = acc;
    }
}

// ---------------- kernel 2: LSTM + softmax weights ----------------
__global__ void __launch_bounds__(128) lstm_kernel(
    const float* __restrict__ x,
    const float* __restrict__ Wih, const float* __restrict__ Whh,
    const float* __restrict__ bih, const float* __restrict__ bhh)
{
    extern __shared__ float sm[];
    float* sWih = sm;                 // 128*65
    float* sWhh = sWih + 128*65;      // 128*33
    float* sx   = sWhh + 128*33;      // 128*64
    float* sh   = sx + 128*64;        // 32
    float* sg   = sh + 32;            // 128
    const int b = blockIdx.x, tid = threadIdx.x;
    for (int i = tid; i < 128*64; i += 128) sWih[(i>>6)*65 + (i&63)] = Wih[i];
    for (int i = tid; i < 128*32; i += 128) sWhh[(i>>5)*33 + (i&31)] = Whh[i];
    for (int i = tid; i < TT*64;  i += 128) sx[i] = x[((i>>6)*BB + b)*64 + (i&63)];
    if (tid < 32) sh[tid] = 0.0f;
    const float bias = bih[tid] + bhh[tid];
    float c = 0.0f;
    __syncthreads();
    for (int t = 0; t < TT; t++){
        float acc = bias;
        const float* wr = sWih + tid*65;
        const float* xr = sx + t*64;
        #pragma unroll 8
        for (int j = 0; j < 64; j++) acc += wr[j]*xr[j];
        const float* hr = sWhh + tid*33;
        #pragma unroll 8
        for (int j = 0; j < 32; j++) acc += hr[j]*sh[j];
        sg[tid] = acc;
        __syncthreads();
        if (tid < 32){
            float ig = 1.0f/(1.0f+expf(-sg[tid]));
            float fg = 1.0f/(1.0f+expf(-sg[32+tid]));
            float gg = tanhf(sg[64+tid]);
            float og = 1.0f/(1.0f+expf(-sg[96+tid]));
            c = fg*c + ig*gg;
            float h = og*tanhf(c);
            sh[tid] = h;
            float m = h;
            for (int o = 16; o; o >>= 1) m = fmaxf(m, __shfl_xor_sync(0xffffffffu, m, o));
            float e = expf(h - m);
            float s = e;
            for (int o = 16; o; o >>= 1) s += __shfl_xor_sync(0xffffffffu, s, o);
            g_w[(t*BB + b)*KK + tid] = e/s;
        }
        __syncthreads();
    }
}

// ---------------- kernel 3: mix A_t, C_t from basis ----------------
__global__ void mix_kernel(const float* __restrict__ AK, const float* __restrict__ CK){
    __shared__ float sB[32*256];
    __shared__ float sw[64*33];
    const int chunk = blockIdx.x;     // 0..15
    const int grp   = blockIdx.y;     // 0..255
    const float* Bsrc = (blockIdx.z == 0) ? AK : CK;
    float* Odst = (blockIdx.z == 0) ? g_A : g_C;
    const int tid = threadIdx.x;      // 256
    for (int i = tid; i < 32*256; i += 256)
        sB[i] = Bsrc[(i>>8)*4096 + chunk*256 + (i&255)];
    for (int i = tid; i < 64*32; i += 256)
        sw[(i>>5)*33 + (i&31)] = g_w[((size_t)grp*64 + (i>>5))*KK + (i&31)];
    __syncthreads();
    const int j = tid;
    for (int tb = 0; tb < 64; tb++){
        float acc = 0.0f;
        const float* wv = sw + tb*33;
        #pragma unroll
        for (int k = 0; k < 32; k++) acc += wv[k]*sB[k*256 + j];
        Odst[(size_t)(grp*64 + tb)*4096 + chunk*256 + j] = acc;
    }
}

// ---------------- kernel 4: Kalman filter (+J gains) ----------------
__global__ void __launch_bounds__(256, 1) filter_kernel(
    const float* __restrict__ as_,
    const float* __restrict__ init_mean,
    const float* __restrict__ init_cov)
{
    extern __shared__ float sm[];
    float* Qs = sm;
    float* Rs = Qs + 64*SD;
    float* As = Rs + 64*SD;
    float* Cs = As + 64*SD;
    float* BP0 = Cs + 64*SD;
    float* BP1 = BP0 + 64*SD;
    float* T1  = BP1 + 64*SD;
    float* T2  = T1 + 64*SD;
    float* T3  = T2 + 64*SD;
    float* vmean = T3 + 64*SD;
    float* vmt   = vmean + 64;
    float* vmn   = vmt + 64;
    float* vin   = vmn + 64;
    float* vat   = vin + 64;
    float* prowbuf = vat + 64;   // 128
    float* scbuf   = prowbuf + 128; // 2 (+pad)
    const int b = blockIdx.x, tid = threadIdx.x;

    for (int i = tid; i < 4096; i += 256){
        int r = i >> 6, c = i & 63;
        BP0[r*SD + c] = init_cov[i];
        Qs[r*SD + c]  = g_Q[i];
        Rs[r*SD + c]  = g_R[i];
    }
    if (tid < 64) vmean[tid] = init_mean[tid];
    __syncthreads();

    float* P  = BP0;
    float* Pn = BP1;

    for (int t = 0; t < TT; t++){
        const int tb = t*BB + b;
        const float* gA = g_A + (size_t)tb*4096;
        const float* gC = g_C + (size_t)tb*4096;
        for (int i4 = tid; i4 < 1024; i4 += 256){
            int r = i4 >> 4, c4 = (i4 & 15) << 2;
            *(float4*)(As + r*SD + c4) = *(const float4*)(gA + r*64 + c4);
            *(float4*)(Cs + r*SD + c4) = *(const float4*)(gC + r*64 + c4);
        }
        if (tid < 64) vat[tid] = as_[(size_t)tb*64 + tid];
        __syncthreads();

        mm_nn(Cs, P, T1, tid);                  // T1 = C P
        mm_nt<true>(T1, Cs, Rs, T2, tid);       // T2 = S = CP C^T + R

        if (tid < 64){                          // vin = a_t - C mean_p (covered by gj's sync)
            float acc = 0.0f;
            #pragma unroll 8
            for (int j = 0; j < 64; j++) acc += Cs[tid*SD + j]*vmean[j];
            vin[tid] = vat[tid] - acc;
        }

        gj_reg(T2, T2, prowbuf, scbuf, tid);    // T2 = S^-1
        mm_nn(T2, T1, T3, tid);                 // T3 = Kt = S^-1 C P

        if (tid < 64){                          // mean_t = mean_p + Kt^T vin
            float acc = vmean[tid];
            #pragma unroll 8
            for (int j = 0; j < 64; j++) acc += T3[j*SD + tid]*vin[j];
            vmt[tid] = acc;
            g_fm[(size_t)tb*64 + tid] = acc;
        }
        __syncthreads();

        mm_tn_sub(T3, T1, P, T2, tid);          // T2 = covt = P - Kt^T (CP)
        symm(T2, tid);
        mm_nn(As, T2, T1, tid);                 // T1 = A covt
        mm_nt<true>(T1, As, Qs, Pn, tid);       // Pn = A covt A^T + Q
        symm(Pn, tid);

        if (tid < 64){                          // mean_n = A mean_t (covered by gj's sync)
            float acc = 0.0f;
            #pragma unroll 8
            for (int j = 0; j < 64; j++) acc += As[tid*SD + j]*vmt[j];
            vmn[tid] = acc;
            if (t == 0) g_mp0[b*64 + tid] = acc;
        }

        gj_reg(Pn, T3, prowbuf, scbuf, tid);    // T3 = Pn^-1 (Pn preserved)
        mm_tn_g(T1, T3, g_J + (size_t)tb*4096, tid); // J = (A covt)^T Pn^-1 -> gmem

        if (tid < 64) vmean[tid] = vmn[tid];
        float* tmp = P; P = Pn; Pn = tmp;       // P <- Pn (pointer swap)
        // loop-head __syncthreads covers vmean/P reuse
    }
}

// ---------------- kernel 5: RTS smoother (means only) ----------------
__global__ void __launch_bounds__(256) smooth_kernel(float* __restrict__ out)
{
    __shared__ float sJ[64*65];
    __shared__ float sv[64];
    __shared__ float sms[64];
    __shared__ float smp0[64];
    const int b = blockIdx.x, tid = threadIdx.x;

    if (tid < 64){
        float m = g_fm[(size_t)((TT-1)*BB + b)*64 + tid];
        sms[tid] = m;
        out[(size_t)((TT-1)*BB + b)*64 + tid] = m;
        smp0[tid] = g_mp0[b*64 + tid];
    }
    float4 rj[4];
    {
        const float* gJ = g_J + (size_t)((TT-2)*BB + b)*4096;
        #pragma unroll
        for (int u = 0; u < 4; u++) rj[u] = *(const float4*)(gJ + (size_t)(tid + 256*u)*4);
    }
    __syncthreads();

    for (int t = TT-2; t >= 0; t--){
        #pragma unroll
        for (int u = 0; u < 4; u++){
            int idx = tid + 256*u;
            int row = idx >> 4, c4 = (idx & 15) << 2;
            sJ[row*65 + c4 + 0] = rj[u].x;
            sJ[row*65 + c4 + 1] = rj[u].y;
            sJ[row*65 + c4 + 2] = rj[u].z;
            sJ[row*65 + c4 + 3] = rj[u].w;
        }
        if (tid < 64) sv[tid] = sms[tid] - smp0[tid];
        __syncthreads();
        if (t > 0){
            const float* gJ = g_J + (size_t)((t-1)*BB + b)*4096;
            #pragma unroll
            for (int u = 0; u < 4; u++) rj[u] = *(const float4*)(gJ + (size_t)(tid + 256*u)*4);
        }
        if (tid < 64){
            float acc = g_fm[(size_t)(t*BB + b)*64 + tid];
            #pragma unroll 8
            for (int j = 0; j < 64; j++) acc += sJ[tid*65 + j]*sv[j];
            out[(size_t)(t*BB + b)*64 + tid] = acc;
            sms[tid] = acc;
        }
        __syncthreads();
    }
}

// ---------------- launch ----------------
extern "C" void kernel_launch(void* const* d_in, const int* in_sizes, int n_in,
                              void* d_out, int out_size)
{
    const float* as_ = (const float*)d_in[0];
    const float* AK  = (const float*)d_in[1];
    const float* CK  = (const float*)d_in[2];
    const float* Lq  = (const float*)d_in[3];
    const float* Lr  = (const float*)d_in[4];
    const float* Wih = (const float*)d_in[5];
    const float* Whh = (const float*)d_in[6];
    const float* bih = (const float*)d_in[7];
    const float* bhh = (const float*)d_in[8];
    const float* im  = (const float*)d_in[9];
    const float* ic  = (const float*)d_in[10];
    float* out = (float*)d_out;

    const int lstm_smem = (128*65 + 128*33 + 128*64 + 32 + 128)*4;
    const int filt_smem = (9*64*SD + 5*64 + 128 + 8)*4;
    cudaFuncSetAttribute(lstm_kernel,   cudaFuncAttributeMaxDynamicSharedMemorySize, lstm_smem);
    cudaFuncSetAttribute(filter_kernel, cudaFuncAttributeMaxDynamicSharedMemorySize, filt_smem);

    qr_kernel<<<2, 256>>>(Lq, Lr);
    lstm_kernel<<<BB, 128, lstm_smem>>>(as_, Wih, Whh, bih, bhh);
    mix_kernel<<<dim3(16, 256, 2), 256>>>(AK, CK);
    filter_kernel<<<BB, 256, filt_smem>>>(as_, im, ic);
    smooth_kernel<<<BB, 256>>>(out);
}